// round 9
// baseline (speedup 1.0000x reference)
#include <cuda_runtime.h>

// Problem constants (fixed by the dataset: node_idx=28, P=320, D=3, sigma=10)
#define NNODE 28
#define PPT   320
#define NPTS  (NNODE * PPT)   // 8960 points per tensor
#define MID   13              // (node_idx-2)/2
#define SIGMA 10.0f

#define HALF_B   160                     // B half-tile size
#define NHB      (2 * NNODE)             // 56 half-rows
#define APT      8                       // A points per thread
#define ANODES   4                       // A nodes per block (8*160/320)
#define STATS_THREADS 128
#define STATS_BLOCKS  (2 * NPTS / STATS_THREADS)   // 140

typedef unsigned long long u64;

// Scratch (no allocations allowed -> device globals)
// g_M[dir][hb * NPTS + pt], hb = 2*node + half : g = aw + min(b.w - a.b)
__device__ float g_M[2][NHB * NPTS];       // 4 MB
__device__ float g_part[STATS_BLOCKS];
__device__ int   g_cnt;

// ---------------------------------------------------------------------------
// Packed f32x2 helpers (Blackwell sm_100+). No packed min exists; mov.b64
// unpack maps to register-pair halves and is elided by ptxas.
// ---------------------------------------------------------------------------
__device__ __forceinline__ u64 pack2(float lo, float hi) {
    u64 r;
    asm("mov.b64 %0, {%1, %2};" : "=l"(r) : "f"(lo), "f"(hi));
    return r;
}
__device__ __forceinline__ u64 fma2(u64 a, u64 b, u64 c) {
    u64 d;
    asm("fma.rn.f32x2 %0, %1, %2, %3;" : "=l"(d) : "l"(a), "l"(b), "l"(c));
    return d;
}
__device__ __forceinline__ void unpack2(u64 v, float& lo, float& hi) {
    asm("mov.b64 {%0, %1}, %2;" : "=f"(lo), "=f"(hi) : "l"(v));
}
__device__ __forceinline__ float clipf(float v) {
    return fminf(fmaxf(v, -SIGMA), SIGMA);
}

// ---------------------------------------------------------------------------
// Kernel 1: per-point per-B-half min of g = a.w + (b.w - a.b)  (clip fused).
// Grid (7, 56, 2), 160 threads. blockIdx.x: 4 A nodes (8 A pts per thread),
// blockIdx.y: B half-tile (node = y>>1, half = y&1, 160 pts in smem),
// blockIdx.z: direction. d = 2*g; the constant a.w shift commutes with all
// the min/second-min algebra in stats. 8 independent fma2 chains per q-iter
// give ILP to hide chain latency at 5 blocks/SM. Resets g_cnt.
// SMEM: sXY[q] = { pack(x2q,x2q+1), pack(y2q,y2q+1) }, sZW likewise z/w.
// ---------------------------------------------------------------------------
__global__ __launch_bounds__(160, 5) void pair_min_kernel(const float* __restrict__ X,
                                                          const float* __restrict__ T) {
    if (blockIdx.x == 0 && blockIdx.y == 0 && blockIdx.z == 0 && threadIdx.x == 0)
        g_cnt = 0;

    const int dir = blockIdx.z;
    const float* __restrict__ Araw = dir ? T : X;
    const float* __restrict__ Braw = dir ? X : T;

    __shared__ ulonglong2 sXY[HALF_B / 2];
    __shared__ ulonglong2 sZW[HALF_B / 2];

    const int t = threadIdx.x;

    // Fill + clip B half-tile (one point per thread)
    {
        const int node = blockIdx.y >> 1, half = blockIdx.y & 1;
        const float* bsrc = Braw + ((size_t)node * PPT + half * HALF_B) * 3;
        float x = clipf(bsrc[3 * t + 0]);
        float y = clipf(bsrc[3 * t + 1]);
        float z = clipf(bsrc[3 * t + 2]);
        float w = fmaf(0.5f * x, x, fmaf(0.5f * y, y, 0.5f * z * z));
        float* fXY = reinterpret_cast<float*>(sXY);
        float* fZW = reinterpret_cast<float*>(sZW);
        int q = t >> 1, r = t & 1;
        fXY[q * 4 + 0 + r] = x;
        fXY[q * 4 + 2 + r] = y;
        fZW[q * 4 + 0 + r] = z;
        fZW[q * 4 + 2 + r] = w;
    }
    __syncthreads();

    // Load + clip 8 A points (4 nodes: base point = blockIdx.x*1280)
    const int aBase = blockIdx.x * (ANODES * PPT);
    const float* asrc = Araw + (size_t)aBase * 3;
    u64 nax[APT], nay[APT], naz[APT];
    float aw[APT];
#pragma unroll
    for (int k = 0; k < APT; k++) {
        int j = t + k * 160;
        float x = clipf(asrc[3 * j + 0]);
        float y = clipf(asrc[3 * j + 1]);
        float z = clipf(asrc[3 * j + 2]);
        aw[k] = fmaf(0.5f * x, x, fmaf(0.5f * y, y, 0.5f * z * z));
        nax[k] = pack2(-x, -x);
        nay[k] = pack2(-y, -y);
        naz[k] = pack2(-z, -z);
    }

    float m[APT];
#pragma unroll
    for (int k = 0; k < APT; k++) m[k] = 3.0e38f;

#pragma unroll 2
    for (int q = 0; q < HALF_B / 2; q++) {
        ulonglong2 bxy = sXY[q];   // .x = packed x pair, .y = packed y pair
        ulonglong2 bzw = sZW[q];   // .x = packed z pair, .y = packed w pair
#pragma unroll
        for (int k = 0; k < APT; k++) {
            u64 f = fma2(naz[k], bzw.x, bzw.y);
            f = fma2(nay[k], bxy.y, f);
            f = fma2(nax[k], bxy.x, f);
            float lo, hi;
            unpack2(f, lo, hi);              // register-pair alias: no SASS cost
            m[k] = fminf(m[k], fminf(lo, hi));
        }
    }

    // Epilogue: coalesced store of aw-shifted mins
    float* __restrict__ Mrow = g_M[dir] + (size_t)blockIdx.y * NPTS + aBase;
#pragma unroll
    for (int k = 0; k < APT; k++) Mrow[t + k * 160] = m[k] + aw[k];
}

// ---------------------------------------------------------------------------
// Kernel 2: per-point closed-form contribution (1 thread per point, 128-thread
// blocks -> 140 blocks: wide SM coverage AND 4 warps/block). All 56 row loads
// batched (MLP~56), perfectly coalesced. Per point in node u with per-node
// mins v[0..27], min m @ argmin a, second-min s, half-range min h:
//   cf = 26*m + (a<=25 ? s-m : 0) + [u<=25]*(v(e)-v(u)) + h ;  contrib = 2*cf
// Final sum fused: last-arriving block's warp 0 reduces the 140 partials in
// fixed lane-strided order (deterministic).
// ---------------------------------------------------------------------------
__global__ __launch_bounds__(STATS_THREADS) void stats_kernel(float* __restrict__ out) {
    const int gp = blockIdx.x * STATS_THREADS + threadIdx.x;   // 0 .. 17919
    const int dir = (gp >= NPTS) ? 1 : 0;
    const int p = gp - dir * NPTS;
    const int u = p / PPT;                                     // node of this point
    const float* __restrict__ Md = g_M[dir] + p;

    // Batched loads: 56 independent LDGs, then fold halves
    float v[NNODE];
#pragma unroll
    for (int j = 0; j < NNODE; j++) {
        float f0 = Md[(size_t)(2 * j + 0) * NPTS];
        float f1 = Md[(size_t)(2 * j + 1) * NPTS];
        v[j] = fminf(f0, f1);
    }

    float m = 3.0e38f, s = 3.0e38f, h = 3.0e38f;
    int a = -1;
    const int h0 = (u < MID) ? 0 : MID;
    const int h1 = (u < MID) ? MID : NNODE;
#pragma unroll
    for (int j = 0; j < NNODE; j++) {
        float vj = v[j];
        if (vj < m) { s = m; m = vj; a = j; }
        else        { s = fminf(s, vj); }
        if (j >= h0 && j < h1) h = fminf(h, vj);
    }

    float cf = 26.0f * m + h;
    if (a <= NNODE - 3) cf += (s - m);                   // a in 0..25
    if (u <= NNODE - 3) {                                // u in 0..25
        int idx_e = (u < MID) ? (u + MID) : (u - MID);
        float v_u = (a == u)     ? s : m;
        float v_e = (a == idx_e) ? s : m;
        cf += v_e - v_u;
    }
    float contrib = 2.0f * cf;

    // Warp butterfly sum, then 4-warp fold in smem
    const int lane = threadIdx.x & 31;
    const int warp = threadIdx.x >> 5;
#pragma unroll
    for (int off = 16; off > 0; off >>= 1)
        contrib += __shfl_xor_sync(0xffffffffu, contrib, off);

    __shared__ float wsum[4];
    if (lane == 0) wsum[warp] = contrib;
    __syncthreads();

    if (warp == 0) {
        float blocksum = (wsum[0] + wsum[1]) + (wsum[2] + wsum[3]);
        int last = 0;
        if (lane == 0) {
            g_part[blockIdx.x] = blocksum;
            __threadfence();
            last = (atomicAdd(&g_cnt, 1) == STATS_BLOCKS - 1);
        }
        last = __shfl_sync(0xffffffffu, last, 0);
        if (last) {
            __threadfence();                              // acquire all g_part
            float ssum = 0.0f;
            for (int i = lane; i < STATS_BLOCKS; i += 32) // fixed order per lane
                ssum += __ldcg(&g_part[i]);
#pragma unroll
            for (int off = 16; off > 0; off >>= 1)
                ssum += __shfl_xor_sync(0xffffffffu, ssum, off);
            if (lane == 0) out[0] = ssum;
        }
    }
}

extern "C" void kernel_launch(void* const* d_in, const int* in_sizes, int n_in,
                              void* d_out, int out_size) {
    const float* X = (const float*)d_in[0];       // X_v        [28,320,3] f32
    const float* T = (const float*)d_in[1];       // target_X_v [28,320,3] f32
    (void)in_sizes; (void)n_in; (void)out_size;   // node_idx fixed at 28

    dim3 g1(NNODE / ANODES, NHB, 2);              // (7, 56, 2)
    pair_min_kernel<<<g1, 160>>>(X, T);

    stats_kernel<<<STATS_BLOCKS, STATS_THREADS>>>((float*)d_out);
}

// round 10
// speedup vs baseline: 1.0601x; 1.0601x over previous
#include <cuda_runtime.h>

#define NNODE 28
#define PPT   320
#define NPTS  (NNODE * PPT)   // 8960
#define MID   13
#define SIGMA 10.0f

#define SN    2               // X nodes per block stripe
#define HALF  160             // T half-tile cols
#define NCP   80              // col pairs per tile
#define NHB   (2 * NNODE)     // 56 T half-tiles
#define NWARP 5

#define STATS_THREADS 512
#define STATS_BLOCKS  (2 * NPTS / STATS_THREADS)   // 35

typedef unsigned long long u64;

// All stored values are d/2. Scratch via device globals (no allocs allowed).
__device__ float g_row[NHB * NPTS];    // [T half][X point]: min d/2 over that T half
__device__ float g_col[NNODE * NPTS];  // [X node][T point]: min d/2 over that X node
__device__ float g_part[STATS_BLOCKS];
__device__ int   g_cnt;

__device__ __forceinline__ u64 pack2(float lo, float hi) {
    u64 r; asm("mov.b64 %0, {%1, %2};" : "=l"(r) : "f"(lo), "f"(hi)); return r;
}
__device__ __forceinline__ u64 fma2(u64 a, u64 b, u64 c) {
    u64 d; asm("fma.rn.f32x2 %0, %1, %2, %3;" : "=l"(d) : "l"(a), "l"(b), "l"(c)); return d;
}
__device__ __forceinline__ u64 add2(u64 a, u64 b) {
    u64 d; asm("add.rn.f32x2 %0, %1, %2;" : "=l"(d) : "l"(a), "l"(b)); return d;
}
__device__ __forceinline__ void unpack2(u64 v, float& lo, float& hi) {
    asm("mov.b64 {%0, %1}, %2;" : "=f"(lo), "=f"(hi) : "l"(v));
}
__device__ __forceinline__ float clipf(float v) { return fminf(fmaxf(v, -SIGMA), SIGMA); }

// ---------------------------------------------------------------------------
// Symmetric tile pass: each (X stripe of 2 nodes) x (T half) tile computed
// ONCE; d/2 = aw + bw - a.b feeds row-mins (X side) AND col-mins (T side).
// Grid (14, 56), 160 threads. Thread t owns rows {t, t+160} (node 2bx) and
// {t+320, t+480} (node 2bx+1); row-mins in regs. Col-mins: rotated colpair
// cp=(t+q)%80 -> distinct per lane in a warp (race-free smem RMW), per-warp
// arrays (race-free across warps), merged in epilogue.
// ---------------------------------------------------------------------------
__global__ __launch_bounds__(160, 6) void pair_min_kernel(const float* __restrict__ X,
                                                          const float* __restrict__ T) {
    if (blockIdx.x == 0 && blockIdx.y == 0 && threadIdx.x == 0) g_cnt = 0;

    __shared__ ulonglong2 sXY[NCP];            // packed (x-pair, y-pair)
    __shared__ ulonglong2 sZW[NCP];            // packed (z-pair, bw-pair)
    __shared__ float2     cmin[NWARP * SN * NCP];

    const int t = threadIdx.x;
    const int w = t >> 5;

    // Fill + clip T half tile (one col per thread)
    {
        const float* bsrc = T + ((size_t)blockIdx.y * HALF) * 3;
        float x = clipf(bsrc[3 * t + 0]);
        float y = clipf(bsrc[3 * t + 1]);
        float z = clipf(bsrc[3 * t + 2]);
        float bw = fmaf(0.5f * x, x, fmaf(0.5f * y, y, 0.5f * z * z));
        float* fXY = reinterpret_cast<float*>(sXY);
        float* fZW = reinterpret_cast<float*>(sZW);
        int q = t >> 1, r = t & 1;
        fXY[q * 4 + 0 + r] = x;
        fXY[q * 4 + 2 + r] = y;
        fZW[q * 4 + 0 + r] = z;
        fZW[q * 4 + 2 + r] = bw;
    }
    for (int i = t; i < NWARP * SN * NCP; i += 160)
        cmin[i] = make_float2(3.0e38f, 3.0e38f);
    __syncthreads();

    // Load + clip 4 X rows
    const int aBase = blockIdx.x * (SN * PPT);
    const float* asrc = X + (size_t)aBase * 3;
    u64 nax[4], nay[4], naz[4], aw2[4];
#pragma unroll
    for (int k = 0; k < 4; k++) {
        int j = t + k * 160;
        float x = clipf(asrc[3 * j + 0]);
        float y = clipf(asrc[3 * j + 1]);
        float z = clipf(asrc[3 * j + 2]);
        float aw = fmaf(0.5f * x, x, fmaf(0.5f * y, y, 0.5f * z * z));
        nax[k] = pack2(-x, -x);
        nay[k] = pack2(-y, -y);
        naz[k] = pack2(-z, -z);
        aw2[k] = pack2(aw, aw);
    }

    float rm[4];
#pragma unroll
    for (int k = 0; k < 4; k++) rm[k] = 3.0e38f;

    float2* __restrict__ cm0 = &cmin[(w * SN + 0) * NCP];
    float2* __restrict__ cm1 = &cmin[(w * SN + 1) * NCP];

    int cp = (t >= NCP) ? t - NCP : t;

#pragma unroll 2
    for (int q = 0; q < NCP; q++) {
        ulonglong2 bxy = sXY[cp];
        ulonglong2 bzw = sZW[cp];

        u64 f0 = fma2(nax[0], bxy.x, fma2(nay[0], bxy.y, fma2(naz[0], bzw.x, add2(bzw.y, aw2[0]))));
        u64 f1 = fma2(nax[1], bxy.x, fma2(nay[1], bxy.y, fma2(naz[1], bzw.x, add2(bzw.y, aw2[1]))));
        u64 f2 = fma2(nax[2], bxy.x, fma2(nay[2], bxy.y, fma2(naz[2], bzw.x, add2(bzw.y, aw2[2]))));
        u64 f3 = fma2(nax[3], bxy.x, fma2(nay[3], bxy.y, fma2(naz[3], bzw.x, add2(bzw.y, aw2[3]))));

        float l0, h0, l1, h1, l2, h2, l3, h3;
        unpack2(f0, l0, h0);
        unpack2(f1, l1, h1);
        unpack2(f2, l2, h2);
        unpack2(f3, l3, h3);

        rm[0] = fminf(rm[0], fminf(l0, h0));
        rm[1] = fminf(rm[1], fminf(l1, h1));
        rm[2] = fminf(rm[2], fminf(l2, h2));
        rm[3] = fminf(rm[3], fminf(l3, h3));

        float2 o0 = cm0[cp];
        cm0[cp] = make_float2(fminf(o0.x, fminf(l0, l1)), fminf(o0.y, fminf(h0, h1)));
        float2 o1 = cm1[cp];
        cm1[cp] = make_float2(fminf(o1.x, fminf(l2, l3)), fminf(o1.y, fminf(h2, h3)));

        cp = (cp == NCP - 1) ? 0 : cp + 1;
    }

    // Row output (coalesced)
    {
        float* __restrict__ R = g_row + (size_t)blockIdx.y * NPTS + aBase;
#pragma unroll
        for (int k = 0; k < 4; k++) R[t + k * 160] = rm[k];
    }

    __syncthreads();

    // Col output: merge 5 warps, store (coalesced within node)
    for (int i = t; i < SN * HALF; i += 160) {
        int node = i / HALF, c = i - node * HALF;
        int p2 = c >> 1, hf = c & 1;
        float v = 3.0e38f;
#pragma unroll
        for (int ww = 0; ww < NWARP; ww++) {
            float2 e = cmin[(ww * SN + node) * NCP + p2];
            v = fminf(v, hf ? e.y : e.x);
        }
        g_col[(size_t)(SN * blockIdx.x + node) * NPTS + blockIdx.y * HALF + c] = v;
    }
}

// ---------------------------------------------------------------------------
// Stats: per-point closed form (values are d/2; contrib = 2*cf).
// dir 0 (X points): v[j] from g_row half pairs; dir 1 (T points): from g_col.
// cf = 26*m + (a<=25 ? s-m : 0) + [u<=25]*(v(e)-v(u)) + h.
// Final sum fused via last-block, fixed-order (deterministic).
// ---------------------------------------------------------------------------
__global__ __launch_bounds__(STATS_THREADS) void stats_kernel(float* __restrict__ out) {
    const int gp = blockIdx.x * STATS_THREADS + threadIdx.x;
    const int dir = (gp >= NPTS) ? 1 : 0;
    const int p = gp - dir * NPTS;
    const int u = p / PPT;

    float v[NNODE];
    if (dir == 0) {
        const float* __restrict__ R = g_row + p;
#pragma unroll
        for (int j = 0; j < NNODE; j++) {
            float f0 = R[(size_t)(2 * j + 0) * NPTS];
            float f1 = R[(size_t)(2 * j + 1) * NPTS];
            v[j] = fminf(f0, f1);
        }
    } else {
        const float* __restrict__ C = g_col + p;
#pragma unroll
        for (int j = 0; j < NNODE; j++) v[j] = C[(size_t)j * NPTS];
    }

    float m = 3.0e38f, s = 3.0e38f, h = 3.0e38f;
    int a = -1;
    const int h0 = (u < MID) ? 0 : MID;
    const int h1 = (u < MID) ? MID : NNODE;
#pragma unroll
    for (int j = 0; j < NNODE; j++) {
        float vj = v[j];
        if (vj < m) { s = m; m = vj; a = j; }
        else        { s = fminf(s, vj); }
        if (j >= h0 && j < h1) h = fminf(h, vj);
    }

    float cf = 26.0f * m + h;
    if (a <= NNODE - 3) cf += (s - m);
    if (u <= NNODE - 3) {
        int idx_e = (u < MID) ? (u + MID) : (u - MID);
        float v_u = (a == u)     ? s : m;
        float v_e = (a == idx_e) ? s : m;
        cf += v_e - v_u;
    }
    float contrib = 2.0f * cf;

    const int lane = threadIdx.x & 31;
    const int warp = threadIdx.x >> 5;
#pragma unroll
    for (int off = 16; off > 0; off >>= 1)
        contrib += __shfl_xor_sync(0xffffffffu, contrib, off);

    __shared__ float wsum[STATS_THREADS / 32];
    if (lane == 0) wsum[warp] = contrib;
    __syncthreads();

    if (warp == 0) {
        float bs = (lane < STATS_THREADS / 32) ? wsum[lane] : 0.0f;
#pragma unroll
        for (int off = 8; off > 0; off >>= 1)
            bs += __shfl_xor_sync(0xffffffffu, bs, off);
        int last = 0;
        if (lane == 0) {
            g_part[blockIdx.x] = bs;
            __threadfence();
            last = (atomicAdd(&g_cnt, 1) == STATS_BLOCKS - 1);
        }
        last = __shfl_sync(0xffffffffu, last, 0);
        if (last) {
            __threadfence();
            float ssum = 0.0f;
            for (int i = lane; i < STATS_BLOCKS; i += 32) ssum += __ldcg(&g_part[i]);
#pragma unroll
            for (int off = 16; off > 0; off >>= 1)
                ssum += __shfl_xor_sync(0xffffffffu, ssum, off);
            if (lane == 0) out[0] = ssum;
        }
    }
}

extern "C" void kernel_launch(void* const* d_in, const int* in_sizes, int n_in,
                              void* d_out, int out_size) {
    const float* X = (const float*)d_in[0];
    const float* T = (const float*)d_in[1];
    (void)in_sizes; (void)n_in; (void)out_size;

    dim3 g1(NNODE / SN, NHB);                 // (14, 56)
    pair_min_kernel<<<g1, 160>>>(X, T);

    stats_kernel<<<STATS_BLOCKS, STATS_THREADS>>>((float*)d_out);
}

// round 11
// speedup vs baseline: 1.0683x; 1.0077x over previous
#include <cuda_runtime.h>

#define NNODE 28
#define PPT   320
#define NPTS  (NNODE * PPT)   // 8960
#define MID   13
#define SIGMA 10.0f

#define SN    4               // X nodes per block stripe (8 rows/thread)
#define HALF  160             // T half-tile cols
#define NCP   80              // col pairs per tile
#define NHB   (2 * NNODE)     // 56 T half-tiles
#define NWARP 5
#define ROWPAD 64             // g_rowT row stride (56 used)
#define COLPAD 32             // g_colT row stride (28 used)

#define STATS_THREADS 128
#define STATS_BLOCKS  (2 * NPTS / STATS_THREADS)   // 140

typedef unsigned long long u64;

// Transposed scratch (d/2 values), sized for contiguous per-point reads.
__device__ float g_rowT[NPTS * ROWPAD];   // [X point][T half]  2.3 MB
__device__ float g_colT[NPTS * COLPAD];   // [T point][X node]  1.15 MB
__device__ float g_part[STATS_BLOCKS];
__device__ int   g_cnt;

__device__ __forceinline__ u64 pack2(float lo, float hi) {
    u64 r; asm("mov.b64 %0, {%1, %2};" : "=l"(r) : "f"(lo), "f"(hi)); return r;
}
__device__ __forceinline__ u64 fma2(u64 a, u64 b, u64 c) {
    u64 d; asm("fma.rn.f32x2 %0, %1, %2, %3;" : "=l"(d) : "l"(a), "l"(b), "l"(c)); return d;
}
__device__ __forceinline__ u64 add2(u64 a, u64 b) {
    u64 d; asm("add.rn.f32x2 %0, %1, %2;" : "=l"(d) : "l"(a), "l"(b)); return d;
}
__device__ __forceinline__ void unpack2(u64 v, float& lo, float& hi) {
    asm("mov.b64 {%0, %1}, %2;" : "=f"(lo), "=f"(hi) : "l"(v));
}
__device__ __forceinline__ float clipf(float v) { return fminf(fmaxf(v, -SIGMA), SIGMA); }

// ---------------------------------------------------------------------------
// Symmetric tile pass. Block = (4 X nodes) x (1 T half); each tile of
// d/2 = aw + bw - a.b computed ONCE, feeding row-mins (regs) and col-mins
// (per-warp smem float4 accumulators, rotated cp = race-free).
// Grid (7, 56), 160 threads, 3 blocks/SM (single wave).
// ---------------------------------------------------------------------------
__global__ __launch_bounds__(160, 3) void pair_min_kernel(const float* __restrict__ X,
                                                          const float* __restrict__ T) {
    if (blockIdx.x == 0 && blockIdx.y == 0 && threadIdx.x == 0) g_cnt = 0;

    __shared__ ulonglong2 sXY[NCP];              // packed (x-pair, y-pair)
    __shared__ ulonglong2 sZW[NCP];              // packed (z-pair, bw-pair)
    __shared__ float4 cminA[NWARP * NCP];        // {n0lo, n0hi, n1lo, n1hi}
    __shared__ float4 cminB[NWARP * NCP];        // {n2lo, n2hi, n3lo, n3hi}

    const int t = threadIdx.x;
    const int w = t >> 5;

    // Fill + clip T half tile (one col per thread)
    {
        const float* bsrc = T + (size_t)blockIdx.y * HALF * 3;
        float x = clipf(bsrc[3 * t + 0]);
        float y = clipf(bsrc[3 * t + 1]);
        float z = clipf(bsrc[3 * t + 2]);
        float bw = fmaf(0.5f * x, x, fmaf(0.5f * y, y, 0.5f * z * z));
        float* fXY = reinterpret_cast<float*>(sXY);
        float* fZW = reinterpret_cast<float*>(sZW);
        int q = t >> 1, r = t & 1;
        fXY[q * 4 + 0 + r] = x;
        fXY[q * 4 + 2 + r] = y;
        fZW[q * 4 + 0 + r] = z;
        fZW[q * 4 + 2 + r] = bw;
    }
    for (int i = t; i < NWARP * NCP; i += 160) {
        cminA[i] = make_float4(3.0e38f, 3.0e38f, 3.0e38f, 3.0e38f);
        cminB[i] = make_float4(3.0e38f, 3.0e38f, 3.0e38f, 3.0e38f);
    }
    __syncthreads();

    // Load + clip 8 X rows (nodes 4*bx .. 4*bx+3; rows k=2n,2n+1 -> node n)
    const int aBase = blockIdx.x * (SN * PPT);
    const float* asrc = X + (size_t)aBase * 3;
    u64 nax[8], nay[8], naz[8], aw2[8];
#pragma unroll
    for (int k = 0; k < 8; k++) {
        int j = t + k * 160;
        float x = clipf(asrc[3 * j + 0]);
        float y = clipf(asrc[3 * j + 1]);
        float z = clipf(asrc[3 * j + 2]);
        float aw = fmaf(0.5f * x, x, fmaf(0.5f * y, y, 0.5f * z * z));
        nax[k] = pack2(-x, -x);
        nay[k] = pack2(-y, -y);
        naz[k] = pack2(-z, -z);
        aw2[k] = pack2(aw, aw);
    }

    float rm[8];
#pragma unroll
    for (int k = 0; k < 8; k++) rm[k] = 3.0e38f;

    float4* __restrict__ cA = &cminA[w * NCP];
    float4* __restrict__ cB = &cminB[w * NCP];

    int cp = (t >= NCP) ? t - NCP : t;   // distinct per lane within each warp

#pragma unroll 2
    for (int q = 0; q < NCP; q++) {
        ulonglong2 bxy = sXY[cp];
        ulonglong2 bzw = sZW[cp];

        float l[8], h[8];
#pragma unroll
        for (int k = 0; k < 8; k++) {
            u64 f = fma2(nax[k], bxy.x,
                     fma2(nay[k], bxy.y,
                      fma2(naz[k], bzw.x, add2(bzw.y, aw2[k]))));
            unpack2(f, l[k], h[k]);
            rm[k] = fminf(rm[k], fminf(l[k], h[k]));
        }

        float4 oa = cA[cp];
        oa.x = fminf(oa.x, fminf(l[0], l[1]));
        oa.y = fminf(oa.y, fminf(h[0], h[1]));
        oa.z = fminf(oa.z, fminf(l[2], l[3]));
        oa.w = fminf(oa.w, fminf(h[2], h[3]));
        cA[cp] = oa;
        float4 ob = cB[cp];
        ob.x = fminf(ob.x, fminf(l[4], l[5]));
        ob.y = fminf(ob.y, fminf(h[4], h[5]));
        ob.z = fminf(ob.z, fminf(l[6], l[7]));
        ob.w = fminf(ob.w, fminf(h[6], h[7]));
        cB[cp] = ob;

        cp = (cp == NCP - 1) ? 0 : cp + 1;
    }

    // Row output: scatter into transposed layout [pt][half]
#pragma unroll
    for (int k = 0; k < 8; k++)
        g_rowT[(size_t)(aBase + t + k * 160) * ROWPAD + blockIdx.y] = rm[k];

    __syncthreads();

    // Col output: merge 5 warps for column t, all 4 nodes; scatter [pt][node]
    {
        const int p2 = t >> 1, hf = t & 1;
        float v0 = 3.0e38f, v1 = 3.0e38f, v2 = 3.0e38f, v3 = 3.0e38f;
#pragma unroll
        for (int ww = 0; ww < NWARP; ww++) {
            float4 a = cminA[ww * NCP + p2];
            float4 b = cminB[ww * NCP + p2];
            v0 = fminf(v0, hf ? a.y : a.x);
            v1 = fminf(v1, hf ? a.w : a.z);
            v2 = fminf(v2, hf ? b.y : b.x);
            v3 = fminf(v3, hf ? b.w : b.z);
        }
        float* dst = g_colT + (size_t)(blockIdx.y * HALF + t) * COLPAD + SN * blockIdx.x;
        dst[0] = v0; dst[1] = v1; dst[2] = v2; dst[3] = v3;
    }
}

// ---------------------------------------------------------------------------
// Stats: per-point closed form from contiguous transposed rows (float4 LDGs).
// dir 0 (X pts): 14 float4 from g_rowT, fold half pairs within each float4.
// dir 1 (T pts): 7 float4 from g_colT.
// cf = 26*m + (a<=25 ? s-m : 0) + [u<=25]*(v(e)-v(u)) + h ;  contrib = 2*cf.
// Fused deterministic final sum via last-arriving block.
// ---------------------------------------------------------------------------
__global__ __launch_bounds__(STATS_THREADS) void stats_kernel(float* __restrict__ out) {
    const int gp = blockIdx.x * STATS_THREADS + threadIdx.x;   // 0..17919
    const int dir = (gp >= NPTS) ? 1 : 0;
    const int p = gp - dir * NPTS;
    const int u = p / PPT;

    float v[NNODE];
    if (dir == 0) {
        const float4* __restrict__ R = reinterpret_cast<const float4*>(
            g_rowT + (size_t)p * ROWPAD);
#pragma unroll
        for (int j4 = 0; j4 < 14; j4++) {
            float4 q = R[j4];
            v[2 * j4 + 0] = fminf(q.x, q.y);
            v[2 * j4 + 1] = fminf(q.z, q.w);
        }
    } else {
        const float4* __restrict__ C = reinterpret_cast<const float4*>(
            g_colT + (size_t)p * COLPAD);
#pragma unroll
        for (int j4 = 0; j4 < 7; j4++) {
            float4 q = C[j4];
            v[4 * j4 + 0] = q.x;
            v[4 * j4 + 1] = q.y;
            v[4 * j4 + 2] = q.z;
            v[4 * j4 + 3] = q.w;
        }
    }

    float m = 3.0e38f, s = 3.0e38f, h = 3.0e38f;
    int a = -1;
    const int h0 = (u < MID) ? 0 : MID;
    const int h1 = (u < MID) ? MID : NNODE;
#pragma unroll
    for (int j = 0; j < NNODE; j++) {
        float vj = v[j];
        if (vj < m) { s = m; m = vj; a = j; }
        else        { s = fminf(s, vj); }
        if (j >= h0 && j < h1) h = fminf(h, vj);
    }

    float cf = 26.0f * m + h;
    if (a <= NNODE - 3) cf += (s - m);
    if (u <= NNODE - 3) {
        int idx_e = (u < MID) ? (u + MID) : (u - MID);
        float v_u = (a == u)     ? s : m;
        float v_e = (a == idx_e) ? s : m;
        cf += v_e - v_u;
    }
    float contrib = 2.0f * cf;

    const int lane = threadIdx.x & 31;
    const int warp = threadIdx.x >> 5;
#pragma unroll
    for (int off = 16; off > 0; off >>= 1)
        contrib += __shfl_xor_sync(0xffffffffu, contrib, off);

    __shared__ float wsum[STATS_THREADS / 32];
    if (lane == 0) wsum[warp] = contrib;
    __syncthreads();

    if (warp == 0) {
        float bs = (wsum[0] + wsum[1]) + (wsum[2] + wsum[3]);
        int last = 0;
        if (lane == 0) {
            g_part[blockIdx.x] = bs;
            __threadfence();
            last = (atomicAdd(&g_cnt, 1) == STATS_BLOCKS - 1);
        }
        last = __shfl_sync(0xffffffffu, last, 0);
        if (last) {
            __threadfence();
            float ssum = 0.0f;
            for (int i = lane; i < STATS_BLOCKS; i += 32)
                ssum += __ldcg(&g_part[i]);
#pragma unroll
            for (int off = 16; off > 0; off >>= 1)
                ssum += __shfl_xor_sync(0xffffffffu, ssum, off);
            if (lane == 0) out[0] = ssum;
        }
    }
}

extern "C" void kernel_launch(void* const* d_in, const int* in_sizes, int n_in,
                              void* d_out, int out_size) {
    const float* X = (const float*)d_in[0];
    const float* T = (const float*)d_in[1];
    (void)in_sizes; (void)n_in; (void)out_size;

    dim3 g1(NNODE / SN, NHB);                 // (7, 56)
    pair_min_kernel<<<g1, 160>>>(X, T);

    stats_kernel<<<STATS_BLOCKS, STATS_THREADS>>>((float*)d_out);
}